// round 5
// baseline (speedup 1.0000x reference)
#include <cuda_runtime.h>
#include <cuda_bf16.h>

#define CIN 64
#define COUT 64
#define NOFFS 26
#define NTAPS 27
#define CSLICES 26                 // center work split into 26 balanced slices
#define YTOT (NOFFS + CSLICES)     // 52
#define THREADS 256
#define WPB (THREADS / 32)         // 8 warps per block
#define GP 16                      // pairs per warp iteration
#define WROW 66                    // weight tile row stride (8B aligned, 2-way write conflict)
#define SROW 68                    // staged s row stride (16B aligned)

typedef unsigned long long u64;

// ---- packed f32x2 helpers (FFMA2 only reachable via PTX) -------------------
__device__ __forceinline__ u64 splat2(float s) {
    u64 r;
    asm("mov.b64 %0, {%1, %1};" : "=l"(r) : "f"(s));
    return r;
}
__device__ __forceinline__ u64 pack2(float a, float b) {
    u64 r;
    asm("mov.b64 %0, {%1, %2};" : "=l"(r) : "f"(a), "f"(b));
    return r;
}
__device__ __forceinline__ u64 ffma2(u64 a, u64 b, u64 c) {
    u64 d;
    asm("fma.rn.f32x2 %0, %1, %2, %3;" : "=l"(d) : "l"(a), "l"(b), "l"(c));
    return d;
}
__device__ __forceinline__ float2 unpack2(u64 v) {
    float2 r;
    asm("mov.b64 {%0, %1}, %2;" : "=f"(r.x), "=f"(r.y) : "l"(v));
    return r;
}

// ----------------------------------------------------------------------------
// Fused kernel. blockIdx.y:
//   0..25  -> neighbor-offset scatter (tap != center), acc starts at 0
//   26..51 -> center slices (tap 13), acc starts at bias
// Lane l owns co = {2l, 2l+1}. Each warp processes GP=16 pairs at once:
// weight row per ci is ONE contiguous 256B LDS.64 (2 phases, no duplication),
// amortized over 16 pairs.
// ----------------------------------------------------------------------------
__global__ __launch_bounds__(THREADS, 3)
void conv_kernel(const float* __restrict__ sp,
                 const float* __restrict__ weight,
                 const float* __restrict__ bias,
                 const int2* __restrict__ nei,
                 const int* __restrict__ sizes,
                 float* __restrict__ out,
                 int P, int n_vox, int chunk) {
    __shared__ __align__(16) float ws[CIN * WROW];            // 16896 B
    __shared__ __align__(16) float srows[WPB][GP][SROW];      // 34816 B

    const int o = blockIdx.y;
    const bool is_center = (o >= NOFFS);
    const int t = is_center ? 13 : (o < 13 ? o : o + 1);

    // transpose weight[co][t][ci] -> ws[ci*WROW + co]
    for (int idx = threadIdx.x; idx < CIN * COUT; idx += THREADS) {
        int ci = idx & (CIN - 1);
        int co = idx >> 6;
        ws[ci * WROW + co] = weight[(co * NTAPS + t) * CIN + ci];
    }
    __syncthreads();

    int size, start = 0;
    long pair_base = 0;
    if (is_center) {
        start = (o - NOFFS) * chunk;
        size = n_vox - start;
        if (size > chunk) size = chunk;
        if (size <= 0) return;
    } else {
        size = sizes[o];
        if (size <= 0) return;
        pair_base = (long)o * P;
    }

    const int lane = threadIdx.x & 31;
    const int wid  = threadIdx.x >> 5;
    const int h    = lane >> 4;    // used for staging only
    const int q    = lane & 15;

    u64 init_acc = 0ull;
    if (is_center) {
        float2 b = __ldg((const float2*)bias + lane);
        init_acc = pack2(b.x, b.y);
    }

    const int ngroups = (size + GP - 1) / GP;

    for (int g = blockIdx.x * WPB + wid; g < ngroups; g += gridDim.x * WPB) {
        const int base_p = g * GP;

        // lanes 0..15 fetch (out,in) for pairs base_p+lane (clamped)
        int oi_r = 0, ii_r = 0;
        if (lane < GP) {
            int p = base_p + lane;
            if (p >= size) p = size - 1;
            if (is_center) {
                oi_r = ii_r = start + p;
            } else {
                int2 pr = __ldg(&nei[pair_base + p]);
                oi_r = pr.x;
                ii_r = pr.y;
            }
        }
        __syncwarp();

        // stage 16 rows (256B each), coalesced: iter i covers rows 2i, 2i+1
#pragma unroll
        for (int i = 0; i < 8; i++) {
            int row = 2 * i + h;
            int ii  = __shfl_sync(0xffffffffu, ii_r, row);
            float4 v = __ldg((const float4*)(sp + (long)ii * CIN) + q);
            *(float4*)&srows[wid][row][q * 4] = v;
        }
        __syncwarp();

        u64 acc[GP];
#pragma unroll
        for (int k = 0; k < GP; k++) acc[k] = init_acc;

#pragma unroll
        for (int c4 = 0; c4 < CIN / 4; c4++) {
            // 4 weight rows for this ci block, contiguous 256B per row
            u64 w0 = *(const u64*)&ws[(4 * c4 + 0) * WROW + 2 * lane];
            u64 w1 = *(const u64*)&ws[(4 * c4 + 1) * WROW + 2 * lane];
            u64 w2 = *(const u64*)&ws[(4 * c4 + 2) * WROW + 2 * lane];
            u64 w3 = *(const u64*)&ws[(4 * c4 + 3) * WROW + 2 * lane];
#pragma unroll
            for (int k = 0; k < GP; k++) {
                float4 sv = *(const float4*)&srows[wid][k][c4 * 4];  // broadcast
                acc[k] = ffma2(splat2(sv.x), w0, acc[k]);
                acc[k] = ffma2(splat2(sv.y), w1, acc[k]);
                acc[k] = ffma2(splat2(sv.z), w2, acc[k]);
                acc[k] = ffma2(splat2(sv.w), w3, acc[k]);
            }
        }

        // epilogue: one RED.64 per pair (256B contiguous per warp)
#pragma unroll
        for (int k = 0; k < GP; k++) {
            int oi = __shfl_sync(0xffffffffu, oi_r, k);
            if (base_p + k < size) {
                atomicAdd((float2*)(out + (long)oi * COUT) + lane,
                          unpack2(acc[k]));
            }
        }
    }
}

// ----------------------------------------------------------------------------
extern "C" void kernel_launch(void* const* d_in, const int* in_sizes, int n_in,
                              void* d_out, int out_size) {
    const float* sp     = (const float*)d_in[0];   // [N, 64]
    const float* weight = (const float*)d_in[1];   // [64, 3,3,3, 64]
    const float* bias   = (const float*)d_in[2];   // [64]
    const int2*  nei    = (const int2*)d_in[3];    // [26, P, 2] -> int2 pairs
    const int*   sizes  = (const int*)d_in[4];     // [26]
    float* out = (float*)d_out;

    const int n_vox = in_sizes[0] / CIN;
    const int P     = in_sizes[3] / (NOFFS * 2);
    const int chunk = (n_vox + CSLICES - 1) / CSLICES;

    // zero output (atomics accumulate onto it; bias added by center slices)
    cudaMemsetAsync(out, 0, (size_t)out_size * sizeof(float), 0);

    dim3 grid(32, YTOT, 1);
    conv_kernel<<<grid, THREADS>>>(sp, weight, bias, nei, sizes, out,
                                   P, n_vox, chunk);
}

// round 6
// speedup vs baseline: 1.8259x; 1.8259x over previous
#include <cuda_runtime.h>
#include <cuda_bf16.h>
#include <cstdint>

#define CIN 64
#define COUT 64
#define NOFFS 26
#define NTAPS 27
#define CSLICES 26                 // center work split into 26 balanced slices
#define YTOT (NOFFS + CSLICES)     // 52
#define THREADS 256
#define WPB (THREADS / 32)         // 8 warps per block
#define GP 16                      // pairs per warp group (= MMA M)
#define SROW 68                    // staged s row stride (floats, conflict-free A reads)
#define GRIDX 8

#define BWS_BYTES (64 * 32 * 16)                    // 64 (kt,nt) tiles x 32 lanes x uint4
#define SROWS_BYTES (WPB * GP * SROW * 4)
#define SMEM_BYTES (BWS_BYTES + SROWS_BYTES)        // 32768 + 34816 = 67584

typedef uint32_t u32;

// ---- tf32 helpers ----------------------------------------------------------
__device__ __forceinline__ u32 f2tf(float f) {
    u32 r;
    asm("cvt.rna.tf32.f32 %0, %1;" : "=r"(r) : "f"(f));
    return r;
}

// D = A(16x8,row) * B(8x8,col) + D, tf32 in / f32 out
__device__ __forceinline__ void mma_tf32(float c[4], u32 a0, u32 a1, u32 a2,
                                         u32 a3, u32 b0, u32 b1) {
    asm volatile(
        "mma.sync.aligned.m16n8k8.row.col.f32.tf32.tf32.f32 "
        "{%0,%1,%2,%3}, {%4,%5,%6,%7}, {%8,%9}, {%0,%1,%2,%3};"
        : "+f"(c[0]), "+f"(c[1]), "+f"(c[2]), "+f"(c[3])
        : "r"(a0), "r"(a1), "r"(a2), "r"(a3), "r"(b0), "r"(b1));
}

// ----------------------------------------------------------------------------
// out[v][:] = bias[:]  (replaces memset; atomics accumulate on top)
// ----------------------------------------------------------------------------
__global__ void bias_init_kernel(const float* __restrict__ bias,
                                 float* __restrict__ out, int total4) {
    int idx = blockIdx.x * blockDim.x + threadIdx.x;
    if (idx < total4) {
        float4 b = __ldg((const float4*)bias + (idx & 15));
        ((float4*)out)[idx] = b;
    }
}

// ----------------------------------------------------------------------------
// Fused scatter kernel. blockIdx.y: 0..25 neighbor offsets, 26..51 center
// slices (tap 13). Each warp processes GP=16 pairs per iteration via
// m16n8k8 tf32 MMAs (3xTF32 split), then scatters with atomicAdd(float2).
// ----------------------------------------------------------------------------
__global__ __launch_bounds__(THREADS, 3)
void conv_kernel(const float* __restrict__ sp,
                 const float* __restrict__ weight,
                 const int2* __restrict__ nei,
                 const int* __restrict__ sizes,
                 float* __restrict__ out,
                 int P, int n_vox, int chunk) {
    extern __shared__ char smem_raw[];
    uint4* bws   = (uint4*)smem_raw;                    // [kt*8+nt][lane] = {bh0,bh1,bl0,bl1}
    float* srows = (float*)(smem_raw + BWS_BYTES);      // [WPB][GP][SROW]

    const int o = blockIdx.y;
    const bool is_center = (o >= NOFFS);
    const int t = is_center ? 13 : (o < 13 ? o : o + 1);

    // Build B fragments (hi/lo tf32 split) directly in mma lane layout:
    // b0: k = kt*8 + (lane&3),     n = nt*8 + (lane>>2)
    // b1: k = kt*8 + (lane&3) + 4, n = nt*8 + (lane>>2)
    for (int idx = threadIdx.x; idx < 64 * 32; idx += THREADS) {
        int lane = idx & 31, tile = idx >> 5;
        int kt = tile >> 3, nt = tile & 7;
        int tig = lane & 3, grp = lane >> 2;
        int co = nt * 8 + grp;
        int k0 = kt * 8 + tig;
        const float* wrow = weight + ((long)co * NTAPS + t) * CIN;
        float w0 = __ldg(&wrow[k0]);
        float w1 = __ldg(&wrow[k0 + 4]);
        u32 h0 = f2tf(w0), h1 = f2tf(w1);
        u32 l0 = f2tf(w0 - __uint_as_float(h0));
        u32 l1 = f2tf(w1 - __uint_as_float(h1));
        bws[tile * 32 + lane] = make_uint4(h0, h1, l0, l1);
    }
    __syncthreads();

    int size, start = 0;
    long pair_base = 0;
    if (is_center) {
        start = (o - NOFFS) * chunk;
        size = n_vox - start;
        if (size > chunk) size = chunk;
        if (size <= 0) return;
    } else {
        size = sizes[o];
        if (size <= 0) return;
        pair_base = (long)o * P;
    }

    const int lane = threadIdx.x & 31;
    const int wid  = threadIdx.x >> 5;
    const int tig  = lane & 3;     // thread-in-group
    const int g    = lane >> 2;    // group id (A/C row base)
    const int h    = lane >> 4;    // staging half
    const int q    = lane & 15;    // staging quad index
    float* srow_w = srows + wid * (GP * SROW);

    const int ngroups = (size + GP - 1) / GP;

    for (int grp = blockIdx.x * WPB + wid; grp < ngroups;
         grp += gridDim.x * WPB) {
        const int base_p = grp * GP;

        // lanes 0..15 fetch (out,in) indices for pairs base_p+lane (clamped)
        int oi_r = 0, ii_r = 0;
        if (lane < GP) {
            int p = base_p + lane;
            if (p >= size) p = size - 1;
            if (is_center) {
                oi_r = ii_r = start + p;
            } else {
                int2 pr = __ldg(&nei[pair_base + p]);
                oi_r = pr.x;
                ii_r = pr.y;
            }
        }
        __syncwarp();

        // stage 16 s-rows (256B each), coalesced; iter i covers rows 2i, 2i+1
#pragma unroll
        for (int i = 0; i < 8; i++) {
            int row = 2 * i + h;
            int ii  = __shfl_sync(0xffffffffu, ii_r, row);
            float4 v = __ldg((const float4*)(sp + (long)ii * CIN) + q);
            *(float4*)&srow_w[row * SROW + q * 4] = v;
        }
        __syncwarp();

        float C[8][4];
#pragma unroll
        for (int nt = 0; nt < 8; nt++) {
            C[nt][0] = 0.f; C[nt][1] = 0.f; C[nt][2] = 0.f; C[nt][3] = 0.f;
        }

#pragma unroll
        for (int kt = 0; kt < 8; kt++) {
            // A fragment (rows = pairs, cols = ci), conflict-free reads
            float a0 = srow_w[g * SROW + kt * 8 + tig];
            float a1 = srow_w[(g + 8) * SROW + kt * 8 + tig];
            float a2 = srow_w[g * SROW + kt * 8 + tig + 4];
            float a3 = srow_w[(g + 8) * SROW + kt * 8 + tig + 4];
            u32 ah0 = f2tf(a0), ah1 = f2tf(a1), ah2 = f2tf(a2), ah3 = f2tf(a3);
            u32 al0 = f2tf(a0 - __uint_as_float(ah0));
            u32 al1 = f2tf(a1 - __uint_as_float(ah1));
            u32 al2 = f2tf(a2 - __uint_as_float(ah2));
            u32 al3 = f2tf(a3 - __uint_as_float(ah3));

#pragma unroll
            for (int nt = 0; nt < 8; nt++) {
                uint4 b = bws[(kt * 8 + nt) * 32 + lane];
                mma_tf32(C[nt], ah0, ah1, ah2, ah3, b.x, b.y);  // hi*hi
                mma_tf32(C[nt], al0, al1, al2, al3, b.x, b.y);  // lo*hi
                mma_tf32(C[nt], ah0, ah1, ah2, ah3, b.z, b.w);  // hi*lo
            }
        }

        // epilogue: C rows g (c0,c1) and g+8 (c2,c3); cols nt*8 + 2*tig{,+1}
        int oi_lo = __shfl_sync(0xffffffffu, oi_r, g);
        int oi_hi = __shfl_sync(0xffffffffu, oi_r, g + 8);
        bool v_lo = (base_p + g)     < size;
        bool v_hi = (base_p + g + 8) < size;
        float* out_lo = out + (long)oi_lo * COUT + 2 * tig;
        float* out_hi = out + (long)oi_hi * COUT + 2 * tig;
#pragma unroll
        for (int nt = 0; nt < 8; nt++) {
            if (v_lo)
                atomicAdd((float2*)(out_lo + nt * 8),
                          make_float2(C[nt][0], C[nt][1]));
            if (v_hi)
                atomicAdd((float2*)(out_hi + nt * 8),
                          make_float2(C[nt][2], C[nt][3]));
        }
    }
}

// ----------------------------------------------------------------------------
extern "C" void kernel_launch(void* const* d_in, const int* in_sizes, int n_in,
                              void* d_out, int out_size) {
    const float* sp     = (const float*)d_in[0];   // [N, 64]
    const float* weight = (const float*)d_in[1];   // [64, 3,3,3, 64]
    const float* bias   = (const float*)d_in[2];   // [64]
    const int2*  nei    = (const int2*)d_in[3];    // [26, P, 2] -> int2 pairs
    const int*   sizes  = (const int*)d_in[4];     // [26]
    float* out = (float*)d_out;

    const int n_vox = in_sizes[0] / CIN;
    const int P     = in_sizes[3] / (NOFFS * 2);
    const int chunk = (n_vox + CSLICES - 1) / CSLICES;

    // allow >48KB dynamic smem (attribute set is idempotent, capture-safe)
    cudaFuncSetAttribute(conv_kernel,
                         cudaFuncAttributeMaxDynamicSharedMemorySize,
                         SMEM_BYTES);

    // initialize out with bias broadcast (replaces memset)
    {
        int total4 = n_vox * (COUT / 4);
        bias_init_kernel<<<(total4 + THREADS - 1) / THREADS, THREADS>>>(
            bias, out, total4);
    }

    dim3 grid(GRIDX, YTOT, 1);
    conv_kernel<<<grid, THREADS, SMEM_BYTES>>>(sp, weight, nei, sizes, out,
                                               P, n_vox, chunk);
}

// round 7
// speedup vs baseline: 1.9930x; 1.0915x over previous
#include <cuda_runtime.h>
#include <cstdint>

#define CIN 64
#define COUT 64
#define NOFFS 26
#define NTAPS 27
#define CSLICES 26                 // center work split into 26 balanced slices
#define YTOT (NOFFS + CSLICES)     // 52
#define THREADS 256
#define WPB (THREADS / 32)         // 8 warps per block
#define GP 16                      // pairs per warp group (= MMA M)
#define GRIDX 8

// staged s rows: per row 32 k-pairs stored as interleaved (hi,lo) bf16x2 u32s
// = 64 u32 data + 8 pad -> stride 72 u32 (conflict-free A-frag LDS.64)
#define SROW_U32 72
#define SROWS_U32 (WPB * GP * SROW_U32)          // 9216 u32 = 36864 B
#define BWS_U32 (32 * 32 * 4)                    // 32 tiles x 32 lanes x uint4 = 16384 B
#define SMEM_BYTES ((BWS_U32 + SROWS_U32) * 4)   // 53248 B

typedef uint32_t u32;

// ---- bf16 split helpers -----------------------------------------------------
// pack two f32 -> bf16x2 (even -> low 16, odd -> high 16); matches the
// production CVT_BF16X2_F32 operand convention.
__device__ __forceinline__ u32 pack_bf16x2(float even, float odd) {
    u32 r;
    asm("cvt.rn.bf16x2.f32 %0, %1, %2;" : "=r"(r) : "f"(odd), "f"(even));
    return r;
}
__device__ __forceinline__ float lo_elem_f(u32 h) { return __uint_as_float(h << 16); }
__device__ __forceinline__ float hi_elem_f(u32 h) { return __uint_as_float(h & 0xffff0000u); }

// split (e,o) into hi-pack and lo-pack (residual) bf16x2
__device__ __forceinline__ void split2(float e, float o, u32& hp, u32& lp) {
    hp = pack_bf16x2(e, o);
    lp = pack_bf16x2(e - lo_elem_f(hp), o - hi_elem_f(hp));
}

// D += A(16x16 bf16, row) * B(16x8 bf16, col), f32 accumulate
__device__ __forceinline__ void mma_bf16(float c[4], u32 a0, u32 a1, u32 a2,
                                         u32 a3, u32 b0, u32 b1) {
    asm volatile(
        "mma.sync.aligned.m16n8k16.row.col.f32.bf16.bf16.f32 "
        "{%0,%1,%2,%3}, {%4,%5,%6,%7}, {%8,%9}, {%0,%1,%2,%3};"
        : "+f"(c[0]), "+f"(c[1]), "+f"(c[2]), "+f"(c[3])
        : "r"(a0), "r"(a1), "r"(a2), "r"(a3), "r"(b0), "r"(b1));
}

// ----------------------------------------------------------------------------
// out[v][:] = bias[:]  (atomics accumulate on top)
// ----------------------------------------------------------------------------
__global__ void bias_init_kernel(const float* __restrict__ bias,
                                 float* __restrict__ out, int total4) {
    int idx = blockIdx.x * blockDim.x + threadIdx.x;
    if (idx < total4) {
        float4 b = __ldg((const float4*)bias + (idx & 15));
        ((float4*)out)[idx] = b;
    }
}

// ----------------------------------------------------------------------------
// Fused scatter kernel. blockIdx.y: 0..25 neighbor offsets, 26..51 center
// slices (tap 13). Each warp handles GP=16 pairs/iteration with bf16 2-term
// split MMAs (hh + lh + hl), then scatters via atomicAdd(float2).
// ----------------------------------------------------------------------------
__global__ __launch_bounds__(THREADS, 3)
void conv_kernel(const float* __restrict__ sp,
                 const float* __restrict__ weight,
                 const int2* __restrict__ nei,
                 const int* __restrict__ sizes,
                 float* __restrict__ out,
                 int P, int n_vox, int chunk) {
    extern __shared__ u32 smem_raw[];
    uint4* bws  = (uint4*)smem_raw;            // [tile=kt*8+nt][lane] = {b0h,b1h,b0l,b1l}
    u32* srows  = smem_raw + BWS_U32;          // [WPB][GP][SROW_U32]

    const int o = blockIdx.y;
    const bool is_center = (o >= NOFFS);
    const int t = is_center ? 13 : (o < 13 ? o : o + 1);

    // Build B fragments (hi/lo bf16 split) in mma.m16n8k16 lane layout:
    // b0: k = kt*16 + 2*(lane&3)+{0,1}, n = nt*8 + (lane>>2); b1: k += 8
    for (int idx = threadIdx.x; idx < 32 * 32; idx += THREADS) {
        int lane = idx & 31, tile = idx >> 5;
        int kt = tile >> 3, nt = tile & 7;
        int n  = nt * 8 + (lane >> 2);
        int k0 = kt * 16 + 2 * (lane & 3);
        const float* wrow = weight + ((long)n * NTAPS + t) * CIN;
        float w0 = __ldg(&wrow[k0]),     w1 = __ldg(&wrow[k0 + 1]);
        float w8 = __ldg(&wrow[k0 + 8]), w9 = __ldg(&wrow[k0 + 9]);
        u32 bh0, bl0, bh1, bl1;
        split2(w0, w1, bh0, bl0);
        split2(w8, w9, bh1, bl1);
        bws[idx] = make_uint4(bh0, bh1, bl0, bl1);
    }
    __syncthreads();

    int size, start = 0;
    long pair_base = 0;
    if (is_center) {
        start = (o - NOFFS) * chunk;
        size = n_vox - start;
        if (size > chunk) size = chunk;
        if (size <= 0) return;
    } else {
        size = sizes[o];
        if (size <= 0) return;
        pair_base = (long)o * P;
    }

    const int lane = threadIdx.x & 31;
    const int wid  = threadIdx.x >> 5;
    const int tig  = lane & 3;     // thread-in-group
    const int g    = lane >> 2;    // group id (A/C row base)
    const int h    = lane >> 4;    // staging half
    const int q    = lane & 15;    // staging quad index
    u32* srow_w = srows + wid * (GP * SROW_U32);

    const int ngroups = (size + GP - 1) / GP;

    for (int grp = blockIdx.x * WPB + wid; grp < ngroups;
         grp += gridDim.x * WPB) {
        const int base_p = grp * GP;

        // lanes 0..15 fetch (out,in) indices for pairs base_p+lane (clamped)
        int oi_r = 0, ii_r = 0;
        if (lane < GP) {
            int p = base_p + lane;
            if (p >= size) p = size - 1;
            if (is_center) {
                oi_r = ii_r = start + p;
            } else {
                int2 pr = __ldg(&nei[pair_base + p]);
                oi_r = pr.x;
                ii_r = pr.y;
            }
        }
        __syncwarp();

        // stage 16 s-rows, pre-split into (hi,lo) bf16x2 pairs; coalesced LDG
#pragma unroll
        for (int i = 0; i < 8; i++) {
            int row = 2 * i + h;
            int ii  = __shfl_sync(0xffffffffu, ii_r, row);
            float4 v = __ldg((const float4*)(sp + (long)ii * CIN) + q);
            u32 h0, l0, h1, l1;
            split2(v.x, v.y, h0, l0);
            split2(v.z, v.w, h1, l1);
            *(uint4*)&srow_w[row * SROW_U32 + q * 4] = make_uint4(h0, l0, h1, l1);
        }
        __syncwarp();

        float C[8][4];
#pragma unroll
        for (int nt = 0; nt < 8; nt++) {
            C[nt][0] = 0.f; C[nt][1] = 0.f; C[nt][2] = 0.f; C[nt][3] = 0.f;
        }

        const u32* r_lo = srow_w + g * SROW_U32 + 2 * tig;
        const u32* r_hi = srow_w + (g + 8) * SROW_U32 + 2 * tig;

#pragma unroll
        for (int kt = 0; kt < 4; kt++) {
            // A fragments: .x = hi pack, .y = lo pack (conflict-free LDS.64)
            uint2 x0 = *(const uint2*)(r_lo + 16 * kt);
            uint2 x1 = *(const uint2*)(r_hi + 16 * kt);
            uint2 x2 = *(const uint2*)(r_lo + 16 * kt + 8);
            uint2 x3 = *(const uint2*)(r_hi + 16 * kt + 8);

#pragma unroll
            for (int nt = 0; nt < 8; nt++) {
                uint4 b = bws[(kt * 8 + nt) * 32 + lane];
                mma_bf16(C[nt], x0.x, x1.x, x2.x, x3.x, b.x, b.y);  // Ah*Bh
                mma_bf16(C[nt], x0.y, x1.y, x2.y, x3.y, b.x, b.y);  // Al*Bh
                mma_bf16(C[nt], x0.x, x1.x, x2.x, x3.x, b.z, b.w);  // Ah*Bl
            }
        }

        // epilogue: C rows g (c0,c1) and g+8 (c2,c3); cols nt*8 + 2*tig{,+1}
        int oi_lo = __shfl_sync(0xffffffffu, oi_r, g);
        int oi_hi = __shfl_sync(0xffffffffu, oi_r, g + 8);
        bool v_lo = (base_p + g)     < size;
        bool v_hi = (base_p + g + 8) < size;
        float* out_lo = out + (long)oi_lo * COUT + 2 * tig;
        float* out_hi = out + (long)oi_hi * COUT + 2 * tig;
#pragma unroll
        for (int nt = 0; nt < 8; nt++) {
            if (v_lo)
                atomicAdd((float2*)(out_lo + nt * 8),
                          make_float2(C[nt][0], C[nt][1]));
            if (v_hi)
                atomicAdd((float2*)(out_hi + nt * 8),
                          make_float2(C[nt][2], C[nt][3]));
        }
    }
}

// ----------------------------------------------------------------------------
extern "C" void kernel_launch(void* const* d_in, const int* in_sizes, int n_in,
                              void* d_out, int out_size) {
    const float* sp     = (const float*)d_in[0];   // [N, 64]
    const float* weight = (const float*)d_in[1];   // [64, 3,3,3, 64]
    const float* bias   = (const float*)d_in[2];   // [64]
    const int2*  nei    = (const int2*)d_in[3];    // [26, P, 2] -> int2 pairs
    const int*   sizes  = (const int*)d_in[4];     // [26]
    float* out = (float*)d_out;

    const int n_vox = in_sizes[0] / CIN;
    const int P     = in_sizes[3] / (NOFFS * 2);
    const int chunk = (n_vox + CSLICES - 1) / CSLICES;

    cudaFuncSetAttribute(conv_kernel,
                         cudaFuncAttributeMaxDynamicSharedMemorySize,
                         SMEM_BYTES);

    // initialize out with bias broadcast
    {
        int total4 = n_vox * (COUT / 4);
        bias_init_kernel<<<(total4 + THREADS - 1) / THREADS, THREADS>>>(
            bias, out, total4);
    }

    dim3 grid(GRIDX, YTOT, 1);
    conv_kernel<<<grid, THREADS, SMEM_BYTES>>>(sp, weight, nei, sizes, out,
                                               P, n_vox, chunk);
}

// round 8
// speedup vs baseline: 2.2692x; 1.1386x over previous
#include <cuda_runtime.h>
#include <cstdint>

#define CIN 64
#define COUT 64
#define NOFFS 26
#define NTAPS 27
#define THREADS 256
#define WPB (THREADS / 32)         // 8 warps per block
#define GP 32                      // pairs per warp iteration (2 x M=16 tiles)
#define GRIDX 11                   // scatter: 11*26 = 286 blocks = 1 wave @ 2/SM

// staged s rows: 32 k-pairs per row as interleaved (hi,lo) bf16x2 u32s
// = 64 u32 data + 4 pad -> stride 68 u32 (A-frag LDS.64 at 2-phase floor)
#define SROW_U32 68
#define SROWS_U32 (WPB * GP * SROW_U32)          // 17408 u32
#define BWS_U32 (32 * 32 * 4)                    // 4096 u32 (32 tiles x 32 lanes x uint4)
#define SMEM_BYTES ((BWS_U32 + SROWS_U32) * 4)   // 86016 B

typedef uint32_t u32;

// ---- bf16 split helpers -----------------------------------------------------
__device__ __forceinline__ u32 pack_bf16x2(float even, float odd) {
    u32 r;
    asm("cvt.rn.bf16x2.f32 %0, %1, %2;" : "=r"(r) : "f"(odd), "f"(even));
    return r;
}
__device__ __forceinline__ float lo_elem_f(u32 h) { return __uint_as_float(h << 16); }
__device__ __forceinline__ float hi_elem_f(u32 h) { return __uint_as_float(h & 0xffff0000u); }
__device__ __forceinline__ void split2(float e, float o, u32& hp, u32& lp) {
    hp = pack_bf16x2(e, o);
    lp = pack_bf16x2(e - lo_elem_f(hp), o - hi_elem_f(hp));
}

// D += A(16x16 bf16,row) * B(16x8 bf16,col), f32 accumulate
__device__ __forceinline__ void mma_bf16(float c[4], u32 a0, u32 a1, u32 a2,
                                         u32 a3, u32 b0, u32 b1) {
    asm volatile(
        "mma.sync.aligned.m16n8k16.row.col.f32.bf16.bf16.f32 "
        "{%0,%1,%2,%3}, {%4,%5,%6,%7}, {%8,%9}, {%0,%1,%2,%3};"
        : "+f"(c[0]), "+f"(c[1]), "+f"(c[2]), "+f"(c[3])
        : "r"(a0), "r"(a1), "r"(a2), "r"(a3), "r"(b0), "r"(b1));
}

// Build B fragments (hi/lo bf16 split) for tap t in mma lane layout.
__device__ __forceinline__ void build_b_tiles(uint4* bws,
                                              const float* __restrict__ weight,
                                              int t) {
    for (int idx = threadIdx.x; idx < 32 * 32; idx += THREADS) {
        int lane = idx & 31, tile = idx >> 5;
        int kt = tile >> 3, nt = tile & 7;
        int n  = nt * 8 + (lane >> 2);
        int k0 = kt * 16 + 2 * (lane & 3);
        const float* wrow = weight + ((long)n * NTAPS + t) * CIN;
        float w0 = __ldg(&wrow[k0]),     w1 = __ldg(&wrow[k0 + 1]);
        float w8 = __ldg(&wrow[k0 + 8]), w9 = __ldg(&wrow[k0 + 9]);
        u32 bh0, bl0, bh1, bl1;
        split2(w0, w1, bh0, bl0);
        split2(w8, w9, bh1, bl1);
        bws[idx] = make_uint4(bh0, bh1, bl0, bl1);
    }
}

// Split a float4 (4 consecutive cols) into two (hi,lo) bf16x2 pairs and store.
__device__ __forceinline__ void stage_row(u32* dst, float4 v) {
    u32 h0, l0, h1, l1;
    split2(v.x, v.y, h0, l0);
    split2(v.z, v.w, h1, l1);
    *(uint4*)dst = make_uint4(h0, l0, h1, l1);
}

// MMA core: 32 pairs (two M=16 tiles) against the 64x64 tap in bws.
// C[m][nt][4]. srow_w = this warp's staged rows.
__device__ __forceinline__ void mma_group(float C[2][8][4], const u32* srow_w,
                                          const uint4* bws, int g, int tig) {
#pragma unroll
    for (int kt = 0; kt < 4; kt++) {
        const u32* p0 = srow_w + g * SROW_U32 + 2 * tig + 16 * kt;
        const u32* p1 = p0 + 8 * SROW_U32;
        const u32* p2 = p0 + 16 * SROW_U32;
        const u32* p3 = p0 + 24 * SROW_U32;
        uint2 x0 = *(const uint2*)p0;          // tile0 row g,   k lo-half
        uint2 x1 = *(const uint2*)p1;          // tile0 row g+8
        uint2 x2 = *(const uint2*)(p0 + 8);    // tile0 row g,   k hi-half
        uint2 x3 = *(const uint2*)(p1 + 8);
        uint2 y0 = *(const uint2*)p2;          // tile1 row 16+g
        uint2 y1 = *(const uint2*)p3;          // tile1 row 24+g
        uint2 y2 = *(const uint2*)(p2 + 8);
        uint2 y3 = *(const uint2*)(p3 + 8);

#pragma unroll
        for (int nt = 0; nt < 8; nt++) {
            uint4 b = bws[(kt * 8 + nt) * 32 + (threadIdx.x & 31)];
            mma_bf16(C[0][nt], x0.x, x1.x, x2.x, x3.x, b.x, b.y);  // Ah*Bh
            mma_bf16(C[0][nt], x0.y, x1.y, x2.y, x3.y, b.x, b.y);  // Al*Bh
            mma_bf16(C[0][nt], x0.x, x1.x, x2.x, x3.x, b.z, b.w);  // Ah*Bl
            mma_bf16(C[1][nt], y0.x, y1.x, y2.x, y3.x, b.x, b.y);
            mma_bf16(C[1][nt], y0.y, y1.y, y2.y, y3.y, b.x, b.y);
            mma_bf16(C[1][nt], y0.x, y1.x, y2.x, y3.x, b.z, b.w);
        }
    }
}

// ----------------------------------------------------------------------------
// Center kernel: out[v] = bias + sp[v] @ Wc  -- plain stores, initializes out.
// ----------------------------------------------------------------------------
__global__ __launch_bounds__(THREADS, 2)
void center_kernel(const float* __restrict__ sp,
                   const float* __restrict__ weight,
                   const float* __restrict__ bias,
                   float* __restrict__ out, int n_vox) {
    extern __shared__ u32 smem_raw[];
    uint4* bws = (uint4*)smem_raw;
    u32* srows = smem_raw + BWS_U32;

    build_b_tiles(bws, weight, 13);
    __syncthreads();

    const int lane = threadIdx.x & 31;
    const int wid  = threadIdx.x >> 5;
    const int tig  = lane & 3;
    const int g    = lane >> 2;
    const int h    = lane >> 4;
    const int q    = lane & 15;
    u32* srow_w = srows + wid * (GP * SROW_U32);

    const int ngroups = (n_vox + GP - 1) / GP;

    for (int grp = blockIdx.x * WPB + wid; grp < ngroups;
         grp += gridDim.x * WPB) {
        const int base_v = grp * GP;

        // stage 32 rows (contiguous voxels), coalesced
#pragma unroll
        for (int i = 0; i < 16; i++) {
            int row = 2 * i + h;
            int v = base_v + row;
            if (v >= n_vox) v = n_vox - 1;
            float4 val = __ldg((const float4*)(sp + (long)v * CIN) + q);
            stage_row(&srow_w[row * SROW_U32 + q * 4], val);
        }
        __syncwarp();

        float C[2][8][4];
#pragma unroll
        for (int m = 0; m < 2; m++)
#pragma unroll
            for (int nt = 0; nt < 8; nt++) {
                C[m][nt][0] = 0.f; C[m][nt][1] = 0.f;
                C[m][nt][2] = 0.f; C[m][nt][3] = 0.f;
            }

        mma_group(C, srow_w, bws, g, tig);

        // plain stores (+bias): tile m rows {16m+g, 16m+8+g}
#pragma unroll
        for (int m = 0; m < 2; m++) {
            int v0 = base_v + 16 * m + g;
            int v1 = v0 + 8;
#pragma unroll
            for (int nt = 0; nt < 8; nt++) {
                float2 b = __ldg((const float2*)bias + nt * 4 + tig);
                if (v0 < n_vox)
                    *(float2*)(out + (long)v0 * COUT + nt * 8 + 2 * tig) =
                        make_float2(C[m][nt][0] + b.x, C[m][nt][1] + b.y);
                if (v1 < n_vox)
                    *(float2*)(out + (long)v1 * COUT + nt * 8 + 2 * tig) =
                        make_float2(C[m][nt][2] + b.x, C[m][nt][3] + b.y);
            }
        }
    }
}

// ----------------------------------------------------------------------------
// Scatter kernel: 26 neighbor offsets, atomicAdd(float2) epilogue.
// ----------------------------------------------------------------------------
__global__ __launch_bounds__(THREADS, 2)
void scatter_kernel(const float* __restrict__ sp,
                    const float* __restrict__ weight,
                    const int2* __restrict__ nei,
                    const int* __restrict__ sizes,
                    float* __restrict__ out, int P) {
    extern __shared__ u32 smem_raw[];
    uint4* bws = (uint4*)smem_raw;
    u32* srows = smem_raw + BWS_U32;

    const int o = blockIdx.y;
    const int t = (o < 13) ? o : o + 1;

    build_b_tiles(bws, weight, t);
    __syncthreads();

    const int size = sizes[o];
    if (size <= 0) return;
    const long pair_base = (long)o * P;

    const int lane = threadIdx.x & 31;
    const int wid  = threadIdx.x >> 5;
    const int tig  = lane & 3;
    const int g    = lane >> 2;
    const int h    = lane >> 4;
    const int q    = lane & 15;
    u32* srow_w = srows + wid * (GP * SROW_U32);

    const int ngroups = (size + GP - 1) / GP;

    for (int grp = blockIdx.x * WPB + wid; grp < ngroups;
         grp += gridDim.x * WPB) {
        const int base_p = grp * GP;

        // every lane fetches one (out,in) pair (clamped)
        int p = base_p + lane;
        if (p >= size) p = size - 1;
        int2 pr = __ldg(&nei[pair_base + p]);
        int oi_r = pr.x, ii_r = pr.y;
        __syncwarp();

        // stage 32 gathered rows
#pragma unroll
        for (int i = 0; i < 16; i++) {
            int row = 2 * i + h;
            int ii  = __shfl_sync(0xffffffffu, ii_r, row);
            float4 val = __ldg((const float4*)(sp + (long)ii * CIN) + q);
            stage_row(&srow_w[row * SROW_U32 + q * 4], val);
        }
        __syncwarp();

        float C[2][8][4];
#pragma unroll
        for (int m = 0; m < 2; m++)
#pragma unroll
            for (int nt = 0; nt < 8; nt++) {
                C[m][nt][0] = 0.f; C[m][nt][1] = 0.f;
                C[m][nt][2] = 0.f; C[m][nt][3] = 0.f;
            }

        mma_group(C, srow_w, bws, g, tig);

        // atomic scatter: tile m rows {16m+g, 16m+8+g}
#pragma unroll
        for (int m = 0; m < 2; m++) {
            int oi0 = __shfl_sync(0xffffffffu, oi_r, 16 * m + g);
            int oi1 = __shfl_sync(0xffffffffu, oi_r, 16 * m + 8 + g);
            bool v0 = (base_p + 16 * m + g)     < size;
            bool v1 = (base_p + 16 * m + 8 + g) < size;
            float* o0 = out + (long)oi0 * COUT + 2 * tig;
            float* o1 = out + (long)oi1 * COUT + 2 * tig;
#pragma unroll
            for (int nt = 0; nt < 8; nt++) {
                if (v0)
                    atomicAdd((float2*)(o0 + nt * 8),
                              make_float2(C[m][nt][0], C[m][nt][1]));
                if (v1)
                    atomicAdd((float2*)(o1 + nt * 8),
                              make_float2(C[m][nt][2], C[m][nt][3]));
            }
        }
    }
}

// ----------------------------------------------------------------------------
extern "C" void kernel_launch(void* const* d_in, const int* in_sizes, int n_in,
                              void* d_out, int out_size) {
    const float* sp     = (const float*)d_in[0];   // [N, 64]
    const float* weight = (const float*)d_in[1];   // [64, 3,3,3, 64]
    const float* bias   = (const float*)d_in[2];   // [64]
    const int2*  nei    = (const int2*)d_in[3];    // [26, P, 2] -> int2 pairs
    const int*   sizes  = (const int*)d_in[4];     // [26]
    float* out = (float*)d_out;

    const int n_vox = in_sizes[0] / CIN;
    const int P     = in_sizes[3] / (NOFFS * 2);

    cudaFuncSetAttribute(center_kernel,
                         cudaFuncAttributeMaxDynamicSharedMemorySize,
                         SMEM_BYTES);
    cudaFuncSetAttribute(scatter_kernel,
                         cudaFuncAttributeMaxDynamicSharedMemorySize,
                         SMEM_BYTES);

    // 1) center tap + bias with plain stores (initializes out)
    {
        int ngroups = (n_vox + GP - 1) / GP;          // ~3125
        int blocks  = (ngroups + WPB - 1) / WPB;      // ~391
        if (blocks > 296) blocks = 296;               // 1 wave @ 2 blocks/SM
        center_kernel<<<blocks, THREADS, SMEM_BYTES>>>(sp, weight, bias, out,
                                                       n_vox);
    }

    // 2) neighbor scatter (stream-ordered after center stores)
    {
        dim3 grid(GRIDX, NOFFS, 1);
        scatter_kernel<<<grid, THREADS, SMEM_BYTES>>>(sp, weight, nei, sizes,
                                                      out, P);
    }
}

// round 9
// speedup vs baseline: 2.4267x; 1.0694x over previous
#include <cuda_runtime.h>
#include <cstdint>

#define CIN 64
#define COUT 64
#define NOFFS 26
#define NTAPS 27
#define THREADS 128
#define WPB (THREADS / 32)         // 4 warps per block
#define GP 32                      // pairs per warp iteration (2 x M=16 tiles)
#define GRIDX 22                   // scatter: 22*26 = 572 blocks ≈ 4/SM

#define BWS_U32 (32 * 32 * 4)                    // 32 tiles x 32 lanes x uint4
#define SMEM_BYTES (BWS_U32 * 4)                 // 16384 B

typedef uint32_t u32;

// ---- bf16 split helpers -----------------------------------------------------
__device__ __forceinline__ u32 pack_bf16x2(float even, float odd) {
    u32 r;
    asm("cvt.rn.bf16x2.f32 %0, %1, %2;" : "=r"(r) : "f"(odd), "f"(even));
    return r;
}
__device__ __forceinline__ float lo_elem_f(u32 h) { return __uint_as_float(h << 16); }
__device__ __forceinline__ float hi_elem_f(u32 h) { return __uint_as_float(h & 0xffff0000u); }
__device__ __forceinline__ void split2(float e, float o, u32& hp, u32& lp) {
    hp = pack_bf16x2(e, o);
    lp = pack_bf16x2(e - lo_elem_f(hp), o - hi_elem_f(hp));
}

// D += A(16x16 bf16,row) * B(16x8 bf16,col), f32 accumulate
__device__ __forceinline__ void mma_bf16(float c[4], u32 a0, u32 a1, u32 a2,
                                         u32 a3, u32 b0, u32 b1) {
    asm volatile(
        "mma.sync.aligned.m16n8k16.row.col.f32.bf16.bf16.f32 "
        "{%0,%1,%2,%3}, {%4,%5,%6,%7}, {%8,%9}, {%0,%1,%2,%3};"
        : "+f"(c[0]), "+f"(c[1]), "+f"(c[2]), "+f"(c[3])
        : "r"(a0), "r"(a1), "r"(a2), "r"(a3), "r"(b0), "r"(b1));
}

// Build B fragments (hi/lo bf16 split) for tap t in mma lane layout.
__device__ __forceinline__ void build_b_tiles(uint4* bws,
                                              const float* __restrict__ weight,
                                              int t) {
    for (int idx = threadIdx.x; idx < 32 * 32; idx += THREADS) {
        int lane = idx & 31, tile = idx >> 5;
        int kt = tile >> 3, nt = tile & 7;
        int n  = nt * 8 + (lane >> 2);
        int k0 = kt * 16 + 2 * (lane & 3);
        const float* wrow = weight + ((long)n * NTAPS + t) * CIN;
        float w0 = __ldg(&wrow[k0]),     w1 = __ldg(&wrow[k0 + 1]);
        float w8 = __ldg(&wrow[k0 + 8]), w9 = __ldg(&wrow[k0 + 9]);
        u32 bh0, bl0, bh1, bl1;
        split2(w0, w1, bh0, bl0);
        split2(w8, w9, bh1, bl1);
        bws[idx] = make_uint4(bh0, bh1, bl0, bl1);
    }
}

// MMA core with DIRECT global A-fragment loads (no smem staging).
// r0..r3 = base pointers of sp rows {g, g+8, 16+g, 24+g} for this lane.
__device__ __forceinline__ void mma_group_direct(float C[2][8][4],
                                                 const float* __restrict__ r0,
                                                 const float* __restrict__ r1,
                                                 const float* __restrict__ r2,
                                                 const float* __restrict__ r3,
                                                 const uint4* __restrict__ bws,
                                                 int lane, int tig) {
#pragma unroll
    for (int kt = 0; kt < 4; kt++) {
        const int c0 = 16 * kt + 2 * tig;
        // tile 0 (rows g, g+8)
        float2 f0 = __ldg((const float2*)(r0 + c0));
        float2 f1 = __ldg((const float2*)(r1 + c0));
        float2 f2 = __ldg((const float2*)(r0 + c0 + 8));
        float2 f3 = __ldg((const float2*)(r1 + c0 + 8));
        // tile 1 (rows 16+g, 24+g)
        float2 e0 = __ldg((const float2*)(r2 + c0));
        float2 e1 = __ldg((const float2*)(r3 + c0));
        float2 e2 = __ldg((const float2*)(r2 + c0 + 8));
        float2 e3 = __ldg((const float2*)(r3 + c0 + 8));

        u32 x0h, x0l, x1h, x1l, x2h, x2l, x3h, x3l;
        split2(f0.x, f0.y, x0h, x0l);
        split2(f1.x, f1.y, x1h, x1l);
        split2(f2.x, f2.y, x2h, x2l);
        split2(f3.x, f3.y, x3h, x3l);
        u32 y0h, y0l, y1h, y1l, y2h, y2l, y3h, y3l;
        split2(e0.x, e0.y, y0h, y0l);
        split2(e1.x, e1.y, y1h, y1l);
        split2(e2.x, e2.y, y2h, y2l);
        split2(e3.x, e3.y, y3h, y3l);

#pragma unroll
        for (int nt = 0; nt < 8; nt++) {
            uint4 b = bws[(kt * 8 + nt) * 32 + lane];
            mma_bf16(C[0][nt], x0h, x1h, x2h, x3h, b.x, b.y);  // Ah*Bh
            mma_bf16(C[0][nt], x0l, x1l, x2l, x3l, b.x, b.y);  // Al*Bh
            mma_bf16(C[0][nt], x0h, x1h, x2h, x3h, b.z, b.w);  // Ah*Bl
            mma_bf16(C[1][nt], y0h, y1h, y2h, y3h, b.x, b.y);
            mma_bf16(C[1][nt], y0l, y1l, y2l, y3l, b.x, b.y);
            mma_bf16(C[1][nt], y0h, y1h, y2h, y3h, b.z, b.w);
        }
    }
}

// ----------------------------------------------------------------------------
// Center kernel: out[v] = bias + sp[v] @ Wc  -- plain stores, initializes out.
// ----------------------------------------------------------------------------
__global__ __launch_bounds__(THREADS, 4)
void center_kernel(const float* __restrict__ sp,
                   const float* __restrict__ weight,
                   const float* __restrict__ bias,
                   float* __restrict__ out, int n_vox) {
    extern __shared__ u32 smem_raw[];
    uint4* bws = (uint4*)smem_raw;

    build_b_tiles(bws, weight, 13);
    __syncthreads();

    const int lane = threadIdx.x & 31;
    const int wid  = threadIdx.x >> 5;
    const int tig  = lane & 3;
    const int g    = lane >> 2;

    const int ngroups = (n_vox + GP - 1) / GP;

    for (int grp = blockIdx.x * WPB + wid; grp < ngroups;
         grp += gridDim.x * WPB) {
        const int base_v = grp * GP;

        int v0 = base_v + g;        if (v0 >= n_vox) v0 = n_vox - 1;
        int v1 = base_v + g + 8;    if (v1 >= n_vox) v1 = n_vox - 1;
        int v2 = base_v + g + 16;   if (v2 >= n_vox) v2 = n_vox - 1;
        int v3 = base_v + g + 24;   if (v3 >= n_vox) v3 = n_vox - 1;

        float C[2][8][4];
#pragma unroll
        for (int m = 0; m < 2; m++)
#pragma unroll
            for (int nt = 0; nt < 8; nt++) {
                C[m][nt][0] = 0.f; C[m][nt][1] = 0.f;
                C[m][nt][2] = 0.f; C[m][nt][3] = 0.f;
            }

        mma_group_direct(C,
                         sp + (long)v0 * CIN, sp + (long)v1 * CIN,
                         sp + (long)v2 * CIN, sp + (long)v3 * CIN,
                         bws, lane, tig);

        // plain stores (+bias): tile m rows {16m+g, 16m+8+g}
#pragma unroll
        for (int m = 0; m < 2; m++) {
            int w0 = base_v + 16 * m + g;
            int w1 = w0 + 8;
#pragma unroll
            for (int nt = 0; nt < 8; nt++) {
                float2 b = __ldg((const float2*)bias + nt * 4 + tig);
                if (w0 < n_vox)
                    *(float2*)(out + (long)w0 * COUT + nt * 8 + 2 * tig) =
                        make_float2(C[m][nt][0] + b.x, C[m][nt][1] + b.y);
                if (w1 < n_vox)
                    *(float2*)(out + (long)w1 * COUT + nt * 8 + 2 * tig) =
                        make_float2(C[m][nt][2] + b.x, C[m][nt][3] + b.y);
            }
        }
    }
}

// ----------------------------------------------------------------------------
// Scatter kernel: 26 neighbor offsets, atomicAdd(float2) epilogue.
// ----------------------------------------------------------------------------
__global__ __launch_bounds__(THREADS, 4)
void scatter_kernel(const float* __restrict__ sp,
                    const float* __restrict__ weight,
                    const int2* __restrict__ nei,
                    const int* __restrict__ sizes,
                    float* __restrict__ out, int P) {
    extern __shared__ u32 smem_raw[];
    uint4* bws = (uint4*)smem_raw;

    const int o = blockIdx.y;
    const int t = (o < 13) ? o : o + 1;

    build_b_tiles(bws, weight, t);
    __syncthreads();

    const int size = sizes[o];
    if (size <= 0) return;
    const long pair_base = (long)o * P;

    const int lane = threadIdx.x & 31;
    const int wid  = threadIdx.x >> 5;
    const int tig  = lane & 3;
    const int g    = lane >> 2;

    const int ngroups = (size + GP - 1) / GP;

    for (int grp = blockIdx.x * WPB + wid; grp < ngroups;
         grp += gridDim.x * WPB) {
        const int base_p = grp * GP;

        // every lane fetches one (out,in) pair (clamped)
        int p = base_p + lane;
        if (p >= size) p = size - 1;
        int2 pr = __ldg(&nei[pair_base + p]);
        int oi_r = pr.x, ii_r = pr.y;
        __syncwarp();

        int i0 = __shfl_sync(0xffffffffu, ii_r, g);
        int i1 = __shfl_sync(0xffffffffu, ii_r, g + 8);
        int i2 = __shfl_sync(0xffffffffu, ii_r, g + 16);
        int i3 = __shfl_sync(0xffffffffu, ii_r, g + 24);

        float C[2][8][4];
#pragma unroll
        for (int m = 0; m < 2; m++)
#pragma unroll
            for (int nt = 0; nt < 8; nt++) {
                C[m][nt][0] = 0.f; C[m][nt][1] = 0.f;
                C[m][nt][2] = 0.f; C[m][nt][3] = 0.f;
            }

        mma_group_direct(C,
                         sp + (long)i0 * CIN, sp + (long)i1 * CIN,
                         sp + (long)i2 * CIN, sp + (long)i3 * CIN,
                         bws, lane, tig);

        // atomic scatter: tile m rows {16m+g, 16m+8+g}
#pragma unroll
        for (int m = 0; m < 2; m++) {
            int oi0 = __shfl_sync(0xffffffffu, oi_r, 16 * m + g);
            int oi1 = __shfl_sync(0xffffffffu, oi_r, 16 * m + 8 + g);
            bool v0 = (base_p + 16 * m + g)     < size;
            bool v1 = (base_p + 16 * m + 8 + g) < size;
            float* o0 = out + (long)oi0 * COUT + 2 * tig;
            float* o1 = out + (long)oi1 * COUT + 2 * tig;
#pragma unroll
            for (int nt = 0; nt < 8; nt++) {
                if (v0)
                    atomicAdd((float2*)(o0 + nt * 8),
                              make_float2(C[m][nt][0], C[m][nt][1]));
                if (v1)
                    atomicAdd((float2*)(o1 + nt * 8),
                              make_float2(C[m][nt][2], C[m][nt][3]));
            }
        }
    }
}

// ----------------------------------------------------------------------------
extern "C" void kernel_launch(void* const* d_in, const int* in_sizes, int n_in,
                              void* d_out, int out_size) {
    const float* sp     = (const float*)d_in[0];   // [N, 64]
    const float* weight = (const float*)d_in[1];   // [64, 3,3,3, 64]
    const float* bias   = (const float*)d_in[2];   // [64]
    const int2*  nei    = (const int2*)d_in[3];    // [26, P, 2] -> int2 pairs
    const int*   sizes  = (const int*)d_in[4];     // [26]
    float* out = (float*)d_out;

    const int n_vox = in_sizes[0] / CIN;
    const int P     = in_sizes[3] / (NOFFS * 2);

    // 1) center tap + bias with plain stores (initializes out)
    {
        int ngroups = (n_vox + GP - 1) / GP;              // ~3125
        int blocks  = (ngroups + WPB - 1) / WPB;
        if (blocks > 592) blocks = 592;                   // ~4 blocks/SM
        center_kernel<<<blocks, THREADS, SMEM_BYTES>>>(sp, weight, bias, out,
                                                       n_vox);
    }

    // 2) neighbor scatter (stream-ordered after center stores)
    {
        dim3 grid(GRIDX, NOFFS, 1);
        scatter_kernel<<<grid, THREADS, SMEM_BYTES>>>(sp, weight, nei, sizes,
                                                      out, P);
    }
}